// round 1
// baseline (speedup 1.0000x reference)
#include <cuda_runtime.h>

#define FULLMASK 0xFFFFFFFFu

namespace {
constexpr int N_SEQ = 4096;
constexpr int T = 128;
constexpr int D = 8;
constexpr float NEG_HALF_LOG2PI = -0.91893853320467274f; // -0.5*log(2*pi)
constexpr int SMEM_FLOATS = 8192 + 2048 + 4096 + 2048 + 64 + 64 + 32 + 32;
}

__device__ float g_enc[(size_t)N_SEQ * T * D];

// ---------------- encoder precompute: enc[n][t][d] = tanh(relu(x*w1+b1) @ w2 + b2)
__global__ void enc_kernel(const float* __restrict__ x,
                           const float* __restrict__ e1w, const float* __restrict__ e1b,
                           const float* __restrict__ e2w, const float* __restrict__ e2b)
{
    __shared__ float s1w[64], s1b[64], s2w[64 * 8], s2b[8];
    int tid = threadIdx.x;
    if (tid < 64) { s1w[tid] = e1w[tid]; s1b[tid] = e1b[tid]; }
    if (tid < 8) s2b[tid] = e2b[tid];
    for (int i = tid; i < 64 * 8; i += blockDim.x) s2w[i] = e2w[i];
    __syncthreads();
    int idx = blockIdx.x * blockDim.x + tid; // n*T + t
    if (idx >= N_SEQ * T) return;
    float xv = x[idx];
    float acc[8];
#pragma unroll
    for (int d = 0; d < 8; d++) acc[d] = s2b[d];
#pragma unroll 8
    for (int h = 0; h < 64; h++) {
        float e = fmaxf(fmaf(xv, s1w[h], s1b[h]), 0.f);
#pragma unroll
        for (int d = 0; d < 8; d++) acc[d] = fmaf(e, s2w[h * 8 + d], acc[d]);
    }
    float4 o0 = make_float4(tanhf(acc[0]), tanhf(acc[1]), tanhf(acc[2]), tanhf(acc[3]));
    float4 o1 = make_float4(tanhf(acc[4]), tanhf(acc[5]), tanhf(acc[6]), tanhf(acc[7]));
    float4* op = reinterpret_cast<float4*>(g_enc + (size_t)idx * 8);
    op[0] = o0;
    op[1] = o1;
}

// ---------------- warp helpers
__device__ __forceinline__ float warp_max(float v)
{
#pragma unroll
    for (int o = 16; o > 0; o >>= 1) v = fmaxf(v, __shfl_xor_sync(FULLMASK, v, o));
    return v;
}
__device__ __forceinline__ float warp_sum(float v)
{
#pragma unroll
    for (int o = 16; o > 0; o >>= 1) v += __shfl_xor_sync(FULLMASK, v, o);
    return v;
}

// phi for 2 sequences sharing every weight load.
// lane L holds component L (and L+32) of each hidden vector.
__device__ __forceinline__ void phi2(float xv0, float xv1, float t0, float t1, int L,
                                     const float* __restrict__ w1_s, const float* __restrict__ w2_s,
                                     const float* __restrict__ wh_s,
                                     const float* __restrict__ b1_s, const float* __restrict__ b2_s,
                                     const float* __restrict__ hb_s,
                                     float& lp0, float& lp1)
{
    float th0 = tanhf(t0), th1 = tanhf(t1);

    float h1a0 = b1_s[L], h1b0 = b1_s[L + 32];
    float h1a1 = h1a0, h1b1 = h1b0;
#pragma unroll 8
    for (int i = 0; i < 32; i++) {
        float wa = w1_s[i * 64 + L];
        float wb = w1_s[i * 64 + 32 + L];
        float v0 = __shfl_sync(FULLMASK, th0, i);
        float v1 = __shfl_sync(FULLMASK, th1, i);
        h1a0 = fmaf(v0, wa, h1a0); h1a1 = fmaf(v1, wa, h1a1);
        h1b0 = fmaf(v0, wb, h1b0); h1b1 = fmaf(v1, wb, h1b1);
    }
    h1a0 = fmaxf(h1a0, 0.f); h1b0 = fmaxf(h1b0, 0.f);
    h1a1 = fmaxf(h1a1, 0.f); h1b1 = fmaxf(h1b1, 0.f);

    float h2a0 = b2_s[L], h2b0 = b2_s[L + 32];
    float h2a1 = h2a0, h2b1 = h2b0;
#pragma unroll 8
    for (int i = 0; i < 32; i++) {
        float wa = w2_s[i * 64 + L];
        float wb = w2_s[i * 64 + 32 + L];
        float v0 = __shfl_sync(FULLMASK, h1a0, i);
        float v1 = __shfl_sync(FULLMASK, h1a1, i);
        h2a0 = fmaf(v0, wa, h2a0); h2a1 = fmaf(v1, wa, h2a1);
        h2b0 = fmaf(v0, wb, h2b0); h2b1 = fmaf(v1, wb, h2b1);
    }
#pragma unroll 8
    for (int i = 0; i < 32; i++) {
        float wa = w2_s[(i + 32) * 64 + L];
        float wb = w2_s[(i + 32) * 64 + 32 + L];
        float v0 = __shfl_sync(FULLMASK, h1b0, i);
        float v1 = __shfl_sync(FULLMASK, h1b1, i);
        h2a0 = fmaf(v0, wa, h2a0); h2a1 = fmaf(v1, wa, h2a1);
        h2b0 = fmaf(v0, wb, h2b0); h2b1 = fmaf(v1, wb, h2b1);
    }
    h2a0 = fmaxf(h2a0, 0.f); h2b0 = fmaxf(h2b0, 0.f);
    h2a1 = fmaxf(h2a1, 0.f); h2b1 = fmaxf(h2b1, 0.f);

    // heads: lane L computes output column L of [mu(0..9) | log_sig(10..19) | alpha(20..29) | 0 pad]
    float o0 = hb_s[L], o1 = o0;
#pragma unroll 8
    for (int i = 0; i < 32; i++) {
        float w = wh_s[i * 32 + L];
        float v0 = __shfl_sync(FULLMASK, h2a0, i);
        float v1 = __shfl_sync(FULLMASK, h2a1, i);
        o0 = fmaf(v0, w, o0); o1 = fmaf(v1, w, o1);
    }
#pragma unroll 8
    for (int i = 0; i < 32; i++) {
        float w = wh_s[(i + 32) * 32 + L];
        float v0 = __shfl_sync(FULLMASK, h2b0, i);
        float v1 = __shfl_sync(FULLMASK, h2b1, i);
        o0 = fmaf(v0, w, o0); o1 = fmaf(v1, w, o1);
    }

    bool valid = (L < 10);
    int src_ls = (L + 10) & 31;
    int src_al = (L + 20) & 31;
    {
        float m  = o0;
        float ls = __shfl_sync(FULLMASK, o0, src_ls);
        float al = __shfl_sync(FULLMASK, o0, src_al);
        float amax = warp_max(valid ? al : -1e30f);
        float asum = warp_sum(valid ? __expf(al - amax) : 0.f);
        float z = (xv0 - m) * __expf(-ls);
        float comp = al - amax - __logf(asum) - 0.5f * z * z - ls + NEG_HALF_LOG2PI;
        float cmax = warp_max(valid ? comp : -1e30f);
        float csum = warp_sum(valid ? __expf(comp - cmax) : 0.f);
        lp0 = cmax + __logf(csum);
    }
    {
        float m  = o1;
        float ls = __shfl_sync(FULLMASK, o1, src_ls);
        float al = __shfl_sync(FULLMASK, o1, src_al);
        float amax = warp_max(valid ? al : -1e30f);
        float asum = warp_sum(valid ? __expf(al - amax) : 0.f);
        float z = (xv1 - m) * __expf(-ls);
        float comp = al - amax - __logf(asum) - 0.5f * z * z - ls + NEG_HALF_LOG2PI;
        float cmax = warp_max(valid ? comp : -1e30f);
        float csum = warp_sum(valid ? __expf(comp - cmax) : 0.f);
        lp1 = cmax + __logf(csum);
    }
}

// ---------------- main scan kernel: 1 warp = 2 sequences, lane = state index
__global__ void __launch_bounds__(256) wfa_kernel(
    const float* __restrict__ x,
    const float* __restrict__ A,
    const float* __restrict__ initw,
    const float* __restrict__ w1, const float* __restrict__ b1,
    const float* __restrict__ w2, const float* __restrict__ b2,
    const float* __restrict__ muw, const float* __restrict__ mub,
    const float* __restrict__ sgw, const float* __restrict__ sgb,
    const float* __restrict__ alw, const float* __restrict__ alb,
    float* __restrict__ out)
{
    extern __shared__ float sm[];
    float* A_s  = sm;           // [ (i*8+d)*32 + j ] : 8192
    float* w1_s = sm + 8192;    // [i][64]            : 2048
    float* w2_s = sm + 10240;   // [k][64]            : 4096
    float* wh_s = sm + 14336;   // [k][32]            : 2048
    float* b1_s = sm + 16384;   // 64
    float* b2_s = sm + 16448;   // 64
    float* hb_s = sm + 16512;   // 32
    float* in_s = sm + 16544;   // 32

    int tid = threadIdx.x;
    for (int i = tid; i < 8192; i += 256) A_s[i] = A[i];
    for (int i = tid; i < 2048; i += 256) w1_s[i] = w1[i];
    for (int i = tid; i < 4096; i += 256) w2_s[i] = w2[i];
    for (int i = tid; i < 2048; i += 256) {
        int k = i >> 5, c = i & 31;
        float v = 0.f;
        if (c < 10) v = muw[k * 10 + c];
        else if (c < 20) v = sgw[k * 10 + (c - 10)];
        else if (c < 30) v = alw[k * 10 + (c - 20)];
        wh_s[i] = v;
    }
    if (tid < 64) { b1_s[tid] = b1[tid]; b2_s[tid] = b2[tid]; }
    if (tid < 32) {
        float v = 0.f;
        if (tid < 10) v = mub[tid];
        else if (tid < 20) v = sgb[tid - 10];
        else if (tid < 30) v = alb[tid - 20];
        hb_s[tid] = v;
        in_s[tid] = initw[tid];
    }
    __syncthreads();

    int warp = (blockIdx.x * 256 + tid) >> 5;
    int L = tid & 31;
    int n0 = warp * 2;

    const float* x0p = x + (size_t)n0 * T;
    const float* x1p = x + (size_t)(n0 + 1) * T;
    const float4* e0p = reinterpret_cast<const float4*>(g_enc + (size_t)n0 * T * 8);
    const float4* e1p = reinterpret_cast<const float4*>(g_enc + (size_t)(n0 + 1) * T * 8);

    float tmp0 = in_s[L], tmp1 = tmp0;
    float res0, res1;
    {
        float lp0, lp1;
        phi2(x0p[0], x1p[0], tmp0, tmp1, L, w1_s, w2_s, wh_s, b1_s, b2_s, hb_s, lp0, lp1);
        res0 = lp0; res1 = lp1;
    }

#pragma unroll 1
    for (int t = 1; t < T; t++) {
        float4 ea0 = e0p[(t - 1) * 2], ea1 = e0p[(t - 1) * 2 + 1];
        float4 eb0 = e1p[(t - 1) * 2], eb1 = e1p[(t - 1) * 2 + 1];

        float B0[8], B1[8];
#pragma unroll
        for (int d = 0; d < 8; d++) { B0[d] = 0.f; B1[d] = 0.f; }
#pragma unroll 4
        for (int i = 0; i < 32; i++) {
            float v0 = __shfl_sync(FULLMASK, tmp0, i);
            float v1 = __shfl_sync(FULLMASK, tmp1, i);
#pragma unroll
            for (int d = 0; d < 8; d++) {
                float a = A_s[(i * 8 + d) * 32 + L];
                B0[d] = fmaf(v0, a, B0[d]);
                B1[d] = fmaf(v1, a, B1[d]);
            }
        }
        tmp0 = fmaf(ea0.x, B0[0], fmaf(ea0.y, B0[1], fmaf(ea0.z, B0[2], fmaf(ea0.w, B0[3],
               fmaf(ea1.x, B0[4], fmaf(ea1.y, B0[5], fmaf(ea1.z, B0[6], ea1.w * B0[7])))))));
        tmp1 = fmaf(eb0.x, B1[0], fmaf(eb0.y, B1[1], fmaf(eb0.z, B1[2], fmaf(eb0.w, B1[3],
               fmaf(eb1.x, B1[4], fmaf(eb1.y, B1[5], fmaf(eb1.z, B1[6], eb1.w * B1[7])))))));

        float lp0, lp1;
        phi2(x0p[t], x1p[t], tmp0, tmp1, L, w1_s, w2_s, wh_s, b1_s, b2_s, hb_s, lp0, lp1);
        res0 += lp0; res1 += lp1;
    }

    if (L == 0) out[n0]     = __expf(res0);
    if (L == 1) out[n0 + 1] = __expf(res1);
}

extern "C" void kernel_launch(void* const* d_in, const int* in_sizes, int n_in,
                              void* d_out, int out_size)
{
    (void)in_sizes; (void)n_in; (void)out_size;
    const float* x   = (const float*)d_in[0];
    const float* e1w = (const float*)d_in[1];
    const float* e1b = (const float*)d_in[2];
    const float* e2w = (const float*)d_in[3];
    const float* e2b = (const float*)d_in[4];
    const float* A   = (const float*)d_in[5];
    const float* iw  = (const float*)d_in[6];
    const float* w1  = (const float*)d_in[7];
    const float* b1  = (const float*)d_in[8];
    const float* w2  = (const float*)d_in[9];
    const float* b2  = (const float*)d_in[10];
    const float* muw = (const float*)d_in[11];
    const float* mub = (const float*)d_in[12];
    const float* sgw = (const float*)d_in[13];
    const float* sgb = (const float*)d_in[14];
    const float* alw = (const float*)d_in[15];
    const float* alb = (const float*)d_in[16];
    float* out = (float*)d_out;

    cudaFuncSetAttribute(wfa_kernel, cudaFuncAttributeMaxDynamicSharedMemorySize,
                         SMEM_FLOATS * (int)sizeof(float));

    enc_kernel<<<(N_SEQ * T + 255) / 256, 256>>>(x, e1w, e1b, e2w, e2b);

    // 4096 sequences, 2 per warp -> 2048 warps -> 256 blocks of 8 warps
    wfa_kernel<<<(N_SEQ / 2) / 8, 256, SMEM_FLOATS * (int)sizeof(float)>>>(
        x, A, iw, w1, b1, w2, b2, muw, mub, sgw, sgb, alw, alb, out);
}

// round 2
// speedup vs baseline: 1.6277x; 1.6277x over previous
#include <cuda_runtime.h>

#define FULLMASK 0xFFFFFFFFu

namespace {
constexpr int N_SEQ = 4096;
constexpr int T = 128;
constexpr float NEG_HALF_LOG2PI = -0.91893853320467274f;
// phi kernel dynamic smem layout (floats):
// w1: 0..2048, w2: 2048..6144, wh: 6144..8192, b1: 8192..8256,
// b2: 8256..8320, hb: 8320..8352, slab: 8352..8352+64*256
constexpr int C_W1 = 0, C_W2 = 2048, C_WH = 6144, C_B1 = 8192, C_B2 = 8256, C_HB = 8320, C_SLAB = 8352;
constexpr int C_SMEM_FLOATS = C_SLAB + 64 * 256;
}

__device__ float g_enc[(size_t)N_SEQ * T * 8];
__device__ float g_th[(size_t)N_SEQ * T * 32];
__device__ float g_logp[(size_t)N_SEQ * T];

typedef unsigned long long u64;

__device__ __forceinline__ u64 pack2(float lo, float hi)
{
    u64 r;
    asm("mov.b64 %0, {%1, %2};" : "=l"(r) : "f"(lo), "f"(hi));
    return r;
}
__device__ __forceinline__ void unpack2(u64 v, float& lo, float& hi)
{
    asm("mov.b64 {%0, %1}, %2;" : "=f"(lo), "=f"(hi) : "l"(v));
}
__device__ __forceinline__ u64 fma2(u64 a, u64 b, u64 c)
{
    u64 d;
    asm("fma.rn.f32x2 %0, %1, %2, %3;" : "=l"(d) : "l"(a), "l"(b), "l"(c));
    return d;
}
__device__ __forceinline__ u64 mul2(u64 a, u64 b)
{
    u64 d;
    asm("mul.rn.f32x2 %0, %1, %2;" : "=l"(d) : "l"(a), "l"(b));
    return d;
}

// ---------------- encoder: g_enc[n][t][d] = tanh(relu(x*w1+b1) @ w2 + b2)
__global__ void enc_kernel(const float* __restrict__ x,
                           const float* __restrict__ e1w, const float* __restrict__ e1b,
                           const float* __restrict__ e2w, const float* __restrict__ e2b)
{
    __shared__ float s1w[64], s1b[64], s2w[64 * 8], s2b[8];
    int tid = threadIdx.x;
    if (tid < 64) { s1w[tid] = e1w[tid]; s1b[tid] = e1b[tid]; }
    if (tid < 8) s2b[tid] = e2b[tid];
    for (int i = tid; i < 64 * 8; i += blockDim.x) s2w[i] = e2w[i];
    __syncthreads();
    int idx = blockIdx.x * blockDim.x + tid;
    if (idx >= N_SEQ * T) return;
    float xv = x[idx];
    float acc[8];
#pragma unroll
    for (int d = 0; d < 8; d++) acc[d] = s2b[d];
#pragma unroll 8
    for (int h = 0; h < 64; h++) {
        float e = fmaxf(fmaf(xv, s1w[h], s1b[h]), 0.f);
#pragma unroll
        for (int d = 0; d < 8; d++) acc[d] = fmaf(e, s2w[h * 8 + d], acc[d]);
    }
    float4 o0 = make_float4(tanhf(acc[0]), tanhf(acc[1]), tanhf(acc[2]), tanhf(acc[3]));
    float4 o1 = make_float4(tanhf(acc[4]), tanhf(acc[5]), tanhf(acc[6]), tanhf(acc[7]));
    float4* op = reinterpret_cast<float4*>(g_enc + (size_t)idx * 8);
    op[0] = o0;
    op[1] = o1;
}

// ---------------- recurrence: warp handles 4 sequences, lane = state j.
// Stores tanh(tmp_t) for all t into g_th.
__global__ void __launch_bounds__(256) rec_kernel(const float* __restrict__ A,
                                                  const float* __restrict__ initw)
{
    __shared__ float2 A2[4096]; // [(i*4+dp)*32 + L] = (A[i][2dp][L], A[i][2dp+1][L])
    __shared__ float in_s[32];
    int tid = threadIdx.x;
    for (int idx = tid; idx < 4096; idx += 256) {
        int i = idx >> 7, dp = (idx >> 5) & 3, L = idx & 31;
        A2[idx] = make_float2(A[(i * 8 + 2 * dp) * 32 + L], A[(i * 8 + 2 * dp + 1) * 32 + L]);
    }
    if (tid < 32) in_s[tid] = initw[tid];
    __syncthreads();

    const u64* A2u = reinterpret_cast<const u64*>(A2);

    int warp = blockIdx.x * 8 + (tid >> 5);
    int L = tid & 31;
    int n0 = warp * 4;

    float tmp[4];
    float init = in_s[L];
#pragma unroll
    for (int s = 0; s < 4; s++) tmp[s] = init;

    float th0 = tanhf(init);
#pragma unroll
    for (int s = 0; s < 4; s++)
        g_th[((size_t)(n0 + s) * T) * 32 + L] = th0;

    const float4* ep[4];
#pragma unroll
    for (int s = 0; s < 4; s++)
        ep[s] = reinterpret_cast<const float4*>(g_enc + (size_t)(n0 + s) * T * 8);

#pragma unroll 1
    for (int t = 1; t < T; t++) {
        u64 B[4][4];
#pragma unroll
        for (int s = 0; s < 4; s++)
#pragma unroll
            for (int dp = 0; dp < 4; dp++) B[s][dp] = 0ull;

#pragma unroll 8
        for (int i = 0; i < 32; i++) {
            u64 v[4];
#pragma unroll
            for (int s = 0; s < 4; s++) {
                float vs = __shfl_sync(FULLMASK, tmp[s], i);
                v[s] = pack2(vs, vs);
            }
#pragma unroll
            for (int dp = 0; dp < 4; dp++) {
                u64 a = A2u[(i * 4 + dp) * 32 + L];
#pragma unroll
                for (int s = 0; s < 4; s++) B[s][dp] = fma2(v[s], a, B[s][dp]);
            }
        }

#pragma unroll
        for (int s = 0; s < 4; s++) {
            float4 e0 = ep[s][(t - 1) * 2];
            float4 e1 = ep[s][(t - 1) * 2 + 1];
            u64 acc = mul2(pack2(e0.x, e0.y), B[s][0]);
            acc = fma2(pack2(e0.z, e0.w), B[s][1], acc);
            acc = fma2(pack2(e1.x, e1.y), B[s][2], acc);
            acc = fma2(pack2(e1.z, e1.w), B[s][3], acc);
            float lo, hi;
            unpack2(acc, lo, hi);
            tmp[s] = lo + hi;
            g_th[((size_t)(n0 + s) * T + t) * 32 + L] = tanhf(tmp[s]);
        }
    }
}

// ---------------- phi: one thread per (n,t) item. Weights broadcast from smem,
// hidden activations staged via per-thread smem slab (lane-stride-1, conflict-free).
__global__ void __launch_bounds__(256) phi_kernel(
    const float* __restrict__ x,
    const float* __restrict__ w1, const float* __restrict__ b1,
    const float* __restrict__ w2, const float* __restrict__ b2,
    const float* __restrict__ muw, const float* __restrict__ mub,
    const float* __restrict__ sgw, const float* __restrict__ sgb,
    const float* __restrict__ alw, const float* __restrict__ alb)
{
    extern __shared__ float sm[];
    int tid = threadIdx.x;

    for (int i = tid; i < 2048; i += 256) sm[C_W1 + i] = w1[i];
    for (int i = tid; i < 4096; i += 256) sm[C_W2 + i] = w2[i];
    for (int i = tid; i < 2048; i += 256) {
        int k = i >> 5, c = i & 31;
        float v = 0.f;
        if (c < 10) v = muw[k * 10 + c];
        else if (c < 20) v = sgw[k * 10 + (c - 10)];
        else if (c < 30) v = alw[k * 10 + (c - 20)];
        sm[C_WH + i] = v;
    }
    if (tid < 64) { sm[C_B1 + tid] = b1[tid]; sm[C_B2 + tid] = b2[tid]; }
    if (tid < 32) {
        float v = 0.f;
        if (tid < 10) v = mub[tid];
        else if (tid < 20) v = sgb[tid - 10];
        else if (tid < 30) v = alb[tid - 20];
        sm[C_HB + tid] = v;
    }
    __syncthreads();

    const ulonglong2* w1v = reinterpret_cast<const ulonglong2*>(sm + C_W1);
    const ulonglong2* w2v = reinterpret_cast<const ulonglong2*>(sm + C_W2);
    const ulonglong2* whv = reinterpret_cast<const ulonglong2*>(sm + C_WH);
    const u64* b1u = reinterpret_cast<const u64*>(sm + C_B1);
    const u64* b2u = reinterpret_cast<const u64*>(sm + C_B2);
    const u64* hbu = reinterpret_cast<const u64*>(sm + C_HB);
    float* slab = sm + C_SLAB;

    int item = blockIdx.x * 256 + tid;
    const float4* thp = reinterpret_cast<const float4*>(g_th + (size_t)item * 32);

    // ---- layer 1: h1[64] = relu(W1^T th + b1)
    u64 hp[32];
#pragma unroll
    for (int p = 0; p < 32; p++) hp[p] = b1u[p];

#pragma unroll 1
    for (int g = 0; g < 8; g++) {
        float4 v4 = thp[g];
        u64 vv0 = pack2(v4.x, v4.x), vv1 = pack2(v4.y, v4.y);
        u64 vv2 = pack2(v4.z, v4.z), vv3 = pack2(v4.w, v4.w);
#pragma unroll
        for (int q = 0; q < 16; q++) {
            ulonglong2 wA = w1v[(g * 4 + 0) * 16 + q];
            hp[2 * q]     = fma2(vv0, wA.x, hp[2 * q]);
            hp[2 * q + 1] = fma2(vv0, wA.y, hp[2 * q + 1]);
            ulonglong2 wB = w1v[(g * 4 + 1) * 16 + q];
            hp[2 * q]     = fma2(vv1, wB.x, hp[2 * q]);
            hp[2 * q + 1] = fma2(vv1, wB.y, hp[2 * q + 1]);
            ulonglong2 wC = w1v[(g * 4 + 2) * 16 + q];
            hp[2 * q]     = fma2(vv2, wC.x, hp[2 * q]);
            hp[2 * q + 1] = fma2(vv2, wC.y, hp[2 * q + 1]);
            ulonglong2 wD = w1v[(g * 4 + 3) * 16 + q];
            hp[2 * q]     = fma2(vv3, wD.x, hp[2 * q]);
            hp[2 * q + 1] = fma2(vv3, wD.y, hp[2 * q + 1]);
        }
    }
    // relu + stage to slab
#pragma unroll
    for (int p = 0; p < 32; p++) {
        float a, b;
        unpack2(hp[p], a, b);
        slab[(2 * p) * 256 + tid]     = fmaxf(a, 0.f);
        slab[(2 * p + 1) * 256 + tid] = fmaxf(b, 0.f);
    }

    // ---- layer 2: h2[64] = relu(W2^T h1 + b2)
#pragma unroll
    for (int p = 0; p < 32; p++) hp[p] = b2u[p];
#pragma unroll 4
    for (int i = 0; i < 64; i++) {
        float v = slab[i * 256 + tid];
        u64 vv = pack2(v, v);
#pragma unroll
        for (int q = 0; q < 16; q++) {
            ulonglong2 w = w2v[i * 16 + q];
            hp[2 * q]     = fma2(vv, w.x, hp[2 * q]);
            hp[2 * q + 1] = fma2(vv, w.y, hp[2 * q + 1]);
        }
    }
#pragma unroll
    for (int p = 0; p < 32; p++) {
        float a, b;
        unpack2(hp[p], a, b);
        slab[(2 * p) * 256 + tid]     = fmaxf(a, 0.f);
        slab[(2 * p + 1) * 256 + tid] = fmaxf(b, 0.f);
    }

    // ---- heads: out[32] = [mu(10) | log_sig(10) | alpha(10) | pad(2)]
    u64 op[16];
#pragma unroll
    for (int p = 0; p < 16; p++) op[p] = hbu[p];
#pragma unroll 4
    for (int k = 0; k < 64; k++) {
        float v = slab[k * 256 + tid];
        u64 vv = pack2(v, v);
#pragma unroll
        for (int q = 0; q < 8; q++) {
            ulonglong2 w = whv[k * 8 + q];
            op[2 * q]     = fma2(vv, w.x, op[2 * q]);
            op[2 * q + 1] = fma2(vv, w.y, op[2 * q + 1]);
        }
    }

    float o[32];
#pragma unroll
    for (int p = 0; p < 16; p++) unpack2(op[p], o[2 * p], o[2 * p + 1]);

    float xv = x[item];
    // alpha log-normalizer
    float amax = o[20];
#pragma unroll
    for (int k = 1; k < 10; k++) amax = fmaxf(amax, o[20 + k]);
    float asum = 0.f;
#pragma unroll
    for (int k = 0; k < 10; k++) asum += __expf(o[20 + k] - amax);
    float lc = amax + __logf(asum);
    // mixture logsumexp
    float comp[10];
    float cmax = -1e30f;
#pragma unroll
    for (int k = 0; k < 10; k++) {
        float ls = o[10 + k];
        float z = (xv - o[k]) * __expf(-ls);
        comp[k] = o[20 + k] - lc - ls + NEG_HALF_LOG2PI - 0.5f * z * z;
        cmax = fmaxf(cmax, comp[k]);
    }
    float csum = 0.f;
#pragma unroll
    for (int k = 0; k < 10; k++) csum += __expf(comp[k] - cmax);
    g_logp[item] = cmax + __logf(csum);
}

// ---------------- reduce: out[n] = exp(sum_t logp[n,t]); warp per n
__global__ void __launch_bounds__(256) red_kernel(float* __restrict__ out)
{
    int wid = threadIdx.x >> 5;
    int L = threadIdx.x & 31;
    int n = blockIdx.x * 8 + wid;
    const float* lp = g_logp + (size_t)n * T;
    float s = lp[L] + lp[L + 32] + lp[L + 64] + lp[L + 96];
#pragma unroll
    for (int o = 16; o > 0; o >>= 1) s += __shfl_xor_sync(FULLMASK, s, o);
    if (L == 0) out[n] = __expf(s);
}

extern "C" void kernel_launch(void* const* d_in, const int* in_sizes, int n_in,
                              void* d_out, int out_size)
{
    (void)in_sizes; (void)n_in; (void)out_size;
    const float* x   = (const float*)d_in[0];
    const float* e1w = (const float*)d_in[1];
    const float* e1b = (const float*)d_in[2];
    const float* e2w = (const float*)d_in[3];
    const float* e2b = (const float*)d_in[4];
    const float* A   = (const float*)d_in[5];
    const float* iw  = (const float*)d_in[6];
    const float* w1  = (const float*)d_in[7];
    const float* b1  = (const float*)d_in[8];
    const float* w2  = (const float*)d_in[9];
    const float* b2  = (const float*)d_in[10];
    const float* muw = (const float*)d_in[11];
    const float* mub = (const float*)d_in[12];
    const float* sgw = (const float*)d_in[13];
    const float* sgb = (const float*)d_in[14];
    const float* alw = (const float*)d_in[15];
    const float* alb = (const float*)d_in[16];
    float* out = (float*)d_out;

    cudaFuncSetAttribute(phi_kernel, cudaFuncAttributeMaxDynamicSharedMemorySize,
                         C_SMEM_FLOATS * (int)sizeof(float));

    enc_kernel<<<(N_SEQ * T + 255) / 256, 256>>>(x, e1w, e1b, e2w, e2b);
    rec_kernel<<<128, 256>>>(A, iw);
    phi_kernel<<<(N_SEQ * T) / 256, 256, C_SMEM_FLOATS * (int)sizeof(float)>>>(
        x, w1, b1, w2, b2, muw, mub, sgw, sgb, alw, alb);
    red_kernel<<<N_SEQ / 8, 256>>>(out);
}

// round 3
// speedup vs baseline: 1.8659x; 1.1463x over previous
#include <cuda_runtime.h>

#define FULLMASK 0xFFFFFFFFu

namespace {
constexpr int N_SEQ = 4096;
constexpr int T = 128;
constexpr float NEG_HALF_LOG2PI = -0.91893853320467274f;
}

__device__ float g_enc[(size_t)N_SEQ * T * 8];
__device__ float g_th[(size_t)N_SEQ * T * 32];
__device__ float g_logp[(size_t)N_SEQ * T];

typedef unsigned long long u64;

__device__ __forceinline__ u64 pack2(float lo, float hi)
{
    u64 r;
    asm("mov.b64 %0, {%1, %2};" : "=l"(r) : "f"(lo), "f"(hi));
    return r;
}
__device__ __forceinline__ void unpack2(u64 v, float& lo, float& hi)
{
    asm("mov.b64 {%0, %1}, %2;" : "=f"(lo), "=f"(hi) : "l"(v));
}
__device__ __forceinline__ u64 fma2(u64 a, u64 b, u64 c)
{
    u64 d;
    asm("fma.rn.f32x2 %0, %1, %2, %3;" : "=l"(d) : "l"(a), "l"(b), "l"(c));
    return d;
}
__device__ __forceinline__ u64 mul2(u64 a, u64 b)
{
    u64 d;
    asm("mul.rn.f32x2 %0, %1, %2;" : "=l"(d) : "l"(a), "l"(b));
    return d;
}

// ---------------- encoder: g_enc[n][t][d] = tanh(relu(x*w1+b1) @ w2 + b2)
__global__ void enc_kernel(const float* __restrict__ x,
                           const float* __restrict__ e1w, const float* __restrict__ e1b,
                           const float* __restrict__ e2w, const float* __restrict__ e2b)
{
    __shared__ float s1w[64], s1b[64], s2w[64 * 8], s2b[8];
    int tid = threadIdx.x;
    if (tid < 64) { s1w[tid] = e1w[tid]; s1b[tid] = e1b[tid]; }
    if (tid < 8) s2b[tid] = e2b[tid];
    for (int i = tid; i < 64 * 8; i += blockDim.x) s2w[i] = e2w[i];
    __syncthreads();
    int idx = blockIdx.x * blockDim.x + tid;
    if (idx >= N_SEQ * T) return;
    float xv = x[idx];
    float acc[8];
#pragma unroll
    for (int d = 0; d < 8; d++) acc[d] = s2b[d];
#pragma unroll 8
    for (int h = 0; h < 64; h++) {
        float e = fmaxf(fmaf(xv, s1w[h], s1b[h]), 0.f);
#pragma unroll
        for (int d = 0; d < 8; d++) acc[d] = fmaf(e, s2w[h * 8 + d], acc[d]);
    }
    float4 o0 = make_float4(tanhf(acc[0]), tanhf(acc[1]), tanhf(acc[2]), tanhf(acc[3]));
    float4 o1 = make_float4(tanhf(acc[4]), tanhf(acc[5]), tanhf(acc[6]), tanhf(acc[7]));
    float4* op = reinterpret_cast<float4*>(g_enc + (size_t)idx * 8);
    op[0] = o0;
    op[1] = o1;
}

// ---------------- recurrence: 2-warp pair handles 4 sequences; each warp does
// half of the i-contraction; partials combined via smem (parity double-buffer).
// Block = 128 threads = 2 pairs = 8 sequences. Grid = 512.
__global__ void __launch_bounds__(128) rec_kernel(const float* __restrict__ A,
                                                  const float* __restrict__ initw)
{
    __shared__ ulonglong2 A4[2048];      // [(i*2+q)*32 + L] = pairs of d: (4q,4q+1),(4q+2,4q+3)
    __shared__ float part[2][4][4][32];  // [parity][warpInBlock][seq][lane]
    __shared__ float in_s[32];

    int tid = threadIdx.x;
    for (int idx = tid; idx < 2048; idx += 128) {
        int i = idx >> 6, q = (idx >> 5) & 1, L = idx & 31;
        const float* base = A + i * 256 + q * 128 + L;
        ulonglong2 v;
        v.x = pack2(base[0], base[32]);
        v.y = pack2(base[64], base[96]);
        A4[idx] = v;
    }
    if (tid < 32) in_s[tid] = initw[tid];
    __syncthreads();

    int wib = tid >> 5;          // 0..3 warp in block
    int pairIB = wib >> 1;       // 0..1
    int half = wib & 1;          // which i half
    int L = tid & 31;
    int pairG = blockIdx.x * 2 + pairIB;
    int n0 = pairG * 4;
    int barId = 1 + pairIB;

    float tmp[4];
    float init = in_s[L];
#pragma unroll
    for (int s = 0; s < 4; s++) tmp[s] = init;

    // t = 0 store
    {
        float th0 = tanhf(init);
        int s0 = half * 2;
        g_th[((size_t)(n0 + s0) * T) * 32 + L] = th0;
        g_th[((size_t)(n0 + s0 + 1) * T) * 32 + L] = th0;
    }

    const float4* ep[4];
#pragma unroll
    for (int s = 0; s < 4; s++)
        ep[s] = reinterpret_cast<const float4*>(g_enc + (size_t)(n0 + s) * T * 8);

    int iBase = half * 16;

#pragma unroll 1
    for (int t = 1; t < T; t++) {
        u64 B[4][4];
#pragma unroll
        for (int s = 0; s < 4; s++)
#pragma unroll
            for (int k = 0; k < 4; k++) B[s][k] = 0ull;

#pragma unroll 8
        for (int ii = 0; ii < 16; ii++) {
            int i = iBase + ii;
            ulonglong2 a0 = A4[(i * 2 + 0) * 32 + L];
            ulonglong2 a1 = A4[(i * 2 + 1) * 32 + L];
#pragma unroll
            for (int s = 0; s < 4; s++) {
                float vs = __shfl_sync(FULLMASK, tmp[s], i);
                u64 vv = pack2(vs, vs);
                B[s][0] = fma2(vv, a0.x, B[s][0]);
                B[s][1] = fma2(vv, a0.y, B[s][1]);
                B[s][2] = fma2(vv, a1.x, B[s][2]);
                B[s][3] = fma2(vv, a1.y, B[s][3]);
            }
        }

        int par = t & 1;
#pragma unroll
        for (int s = 0; s < 4; s++) {
            float4 e0 = ep[s][(t - 1) * 2];
            float4 e1 = ep[s][(t - 1) * 2 + 1];
            u64 acc = mul2(pack2(e0.x, e0.y), B[s][0]);
            acc = fma2(pack2(e0.z, e0.w), B[s][1], acc);
            acc = fma2(pack2(e1.x, e1.y), B[s][2], acc);
            acc = fma2(pack2(e1.z, e1.w), B[s][3], acc);
            float lo, hi;
            unpack2(acc, lo, hi);
            part[par][wib][s][L] = lo + hi;
        }

        asm volatile("bar.sync %0, 64;" :: "r"(barId) : "memory");

        int partner = wib ^ 1;
#pragma unroll
        for (int s = 0; s < 4; s++)
            tmp[s] = part[par][wib][s][L] + part[par][partner][s][L];

        // store tanh for the two sequences this warp owns
        int s0 = half * 2;
        g_th[((size_t)(n0 + s0) * T + t) * 32 + L] = tanhf(tmp[s0]);
        g_th[((size_t)(n0 + s0 + 1) * T + t) * 32 + L] = tanhf(tmp[s0 + 1]);
    }
}

// ---------------- phi: one thread per (n,t) item; weights broadcast from smem;
// hidden activations fully register-resident (full unroll, no slab).
__global__ void __launch_bounds__(256) phi_kernel(
    const float* __restrict__ x,
    const float* __restrict__ w1, const float* __restrict__ b1,
    const float* __restrict__ w2, const float* __restrict__ b2,
    const float* __restrict__ muw, const float* __restrict__ mub,
    const float* __restrict__ sgw, const float* __restrict__ sgb,
    const float* __restrict__ alw, const float* __restrict__ alb)
{
    __shared__ float sm[8352];
    int tid = threadIdx.x;

    for (int i = tid; i < 2048; i += 256) sm[i] = w1[i];
    for (int i = tid; i < 4096; i += 256) sm[2048 + i] = w2[i];
    for (int i = tid; i < 2048; i += 256) {
        int k = i >> 5, c = i & 31;
        float v = 0.f;
        if (c < 10) v = muw[k * 10 + c];
        else if (c < 20) v = sgw[k * 10 + (c - 10)];
        else if (c < 30) v = alw[k * 10 + (c - 20)];
        sm[6144 + i] = v;
    }
    if (tid < 64) { sm[8192 + tid] = b1[tid]; sm[8256 + tid] = b2[tid]; }
    if (tid < 32) {
        float v = 0.f;
        if (tid < 10) v = mub[tid];
        else if (tid < 20) v = sgb[tid - 10];
        else if (tid < 30) v = alb[tid - 20];
        sm[8320 + tid] = v;
    }
    __syncthreads();

    const ulonglong2* w1v = reinterpret_cast<const ulonglong2*>(sm);
    const ulonglong2* w2v = reinterpret_cast<const ulonglong2*>(sm + 2048);
    const ulonglong2* whv = reinterpret_cast<const ulonglong2*>(sm + 6144);
    const u64* b1u = reinterpret_cast<const u64*>(sm + 8192);
    const u64* b2u = reinterpret_cast<const u64*>(sm + 8256);
    const u64* hbu = reinterpret_cast<const u64*>(sm + 8320);

    int item = blockIdx.x * 256 + tid;
    const float4* thp = reinterpret_cast<const float4*>(g_th + (size_t)item * 32);

    // ---- layer 1: h1[64] = relu(W1^T th + b1), accumulate in u64 pairs
    u64 hp[32];
#pragma unroll
    for (int p = 0; p < 32; p++) hp[p] = b1u[p];

#pragma unroll
    for (int g = 0; g < 8; g++) {
        float4 v4 = thp[g];
        u64 vv0 = pack2(v4.x, v4.x), vv1 = pack2(v4.y, v4.y);
        u64 vv2 = pack2(v4.z, v4.z), vv3 = pack2(v4.w, v4.w);
#pragma unroll
        for (int q = 0; q < 16; q++) {
            ulonglong2 wA = w1v[(g * 4 + 0) * 16 + q];
            hp[2 * q]     = fma2(vv0, wA.x, hp[2 * q]);
            hp[2 * q + 1] = fma2(vv0, wA.y, hp[2 * q + 1]);
            ulonglong2 wB = w1v[(g * 4 + 1) * 16 + q];
            hp[2 * q]     = fma2(vv1, wB.x, hp[2 * q]);
            hp[2 * q + 1] = fma2(vv1, wB.y, hp[2 * q + 1]);
            ulonglong2 wC = w1v[(g * 4 + 2) * 16 + q];
            hp[2 * q]     = fma2(vv2, wC.x, hp[2 * q]);
            hp[2 * q + 1] = fma2(vv2, wC.y, hp[2 * q + 1]);
            ulonglong2 wD = w1v[(g * 4 + 3) * 16 + q];
            hp[2 * q]     = fma2(vv3, wD.x, hp[2 * q]);
            hp[2 * q + 1] = fma2(vv3, wD.y, hp[2 * q + 1]);
        }
    }
    float h1f[64];
#pragma unroll
    for (int p = 0; p < 32; p++) unpack2(hp[p], h1f[2 * p], h1f[2 * p + 1]);

    // ---- layer 2: h2[64] = relu(W2^T relu(h1) + b2)
    u64 h2[32];
#pragma unroll
    for (int p = 0; p < 32; p++) h2[p] = b2u[p];
#pragma unroll
    for (int i = 0; i < 64; i++) {
        float r = fmaxf(h1f[i], 0.f);
        u64 vv = pack2(r, r);
#pragma unroll
        for (int q = 0; q < 16; q++) {
            ulonglong2 w = w2v[i * 16 + q];
            h2[2 * q]     = fma2(vv, w.x, h2[2 * q]);
            h2[2 * q + 1] = fma2(vv, w.y, h2[2 * q + 1]);
        }
    }
    float h2f[64];
#pragma unroll
    for (int p = 0; p < 32; p++) unpack2(h2[p], h2f[2 * p], h2f[2 * p + 1]);

    // ---- heads
    u64 op[16];
#pragma unroll
    for (int p = 0; p < 16; p++) op[p] = hbu[p];
#pragma unroll
    for (int k = 0; k < 64; k++) {
        float r = fmaxf(h2f[k], 0.f);
        u64 vv = pack2(r, r);
#pragma unroll
        for (int q = 0; q < 8; q++) {
            ulonglong2 w = whv[k * 8 + q];
            op[2 * q]     = fma2(vv, w.x, op[2 * q]);
            op[2 * q + 1] = fma2(vv, w.y, op[2 * q + 1]);
        }
    }

    float o[32];
#pragma unroll
    for (int p = 0; p < 16; p++) unpack2(op[p], o[2 * p], o[2 * p + 1]);

    float xv = x[item];
    float amax = o[20];
#pragma unroll
    for (int k = 1; k < 10; k++) amax = fmaxf(amax, o[20 + k]);
    float asum = 0.f;
#pragma unroll
    for (int k = 0; k < 10; k++) asum += __expf(o[20 + k] - amax);
    float lc = amax + __logf(asum);

    float comp[10];
    float cmax = -1e30f;
#pragma unroll
    for (int k = 0; k < 10; k++) {
        float ls = o[10 + k];
        float z = (xv - o[k]) * __expf(-ls);
        comp[k] = o[20 + k] - lc - ls + NEG_HALF_LOG2PI - 0.5f * z * z;
        cmax = fmaxf(cmax, comp[k]);
    }
    float csum = 0.f;
#pragma unroll
    for (int k = 0; k < 10; k++) csum += __expf(comp[k] - cmax);
    g_logp[item] = cmax + __logf(csum);
}

// ---------------- reduce: out[n] = exp(sum_t logp[n,t]); warp per n
__global__ void __launch_bounds__(256) red_kernel(float* __restrict__ out)
{
    int wid = threadIdx.x >> 5;
    int L = threadIdx.x & 31;
    int n = blockIdx.x * 8 + wid;
    const float* lp = g_logp + (size_t)n * T;
    float s = lp[L] + lp[L + 32] + lp[L + 64] + lp[L + 96];
#pragma unroll
    for (int o = 16; o > 0; o >>= 1) s += __shfl_xor_sync(FULLMASK, s, o);
    if (L == 0) out[n] = __expf(s);
}

extern "C" void kernel_launch(void* const* d_in, const int* in_sizes, int n_in,
                              void* d_out, int out_size)
{
    (void)in_sizes; (void)n_in; (void)out_size;
    const float* x   = (const float*)d_in[0];
    const float* e1w = (const float*)d_in[1];
    const float* e1b = (const float*)d_in[2];
    const float* e2w = (const float*)d_in[3];
    const float* e2b = (const float*)d_in[4];
    const float* A   = (const float*)d_in[5];
    const float* iw  = (const float*)d_in[6];
    const float* w1  = (const float*)d_in[7];
    const float* b1  = (const float*)d_in[8];
    const float* w2  = (const float*)d_in[9];
    const float* b2  = (const float*)d_in[10];
    const float* muw = (const float*)d_in[11];
    const float* mub = (const float*)d_in[12];
    const float* sgw = (const float*)d_in[13];
    const float* sgb = (const float*)d_in[14];
    const float* alw = (const float*)d_in[15];
    const float* alb = (const float*)d_in[16];
    float* out = (float*)d_out;

    enc_kernel<<<(N_SEQ * T + 255) / 256, 256>>>(x, e1w, e1b, e2w, e2b);
    rec_kernel<<<512, 128>>>(A, iw);
    phi_kernel<<<(N_SEQ * T) / 256, 256>>>(
        x, w1, b1, w2, b2, muw, mub, sgw, sgb, alw, alb);
    red_kernel<<<N_SEQ / 8, 256>>>(out);
}